// round 12
// baseline (speedup 1.0000x reference)
#include <cuda_runtime.h>
#include <cuda_fp16.h>
#include <cstdint>

#define NB 32
#define NN 2000
#define NE 64000
#define ND 128
#define WCHUNK 5

// ---------------- scratch ----------------
__device__ int    g_cursor[NN];
__device__ float  g_dinv[NN];
__device__ float  g_selfn[NN];
__device__ float  g_c[NN];
__device__ int    g_rs[NN + 1];
__device__ int2   g_csr[NE];            // (src*16 [uint4 units], w packed half2)
__device__ float  g_v[NB * ND];
__device__ __half g_h1[(size_t)NB * NN * ND];  // layer-1 output, fp16 (16.4 MB)

__device__ __forceinline__ __half2 u2h2(unsigned u) { return *reinterpret_cast<__half2*>(&u); }

// ---------------- prep: count(smem) + scan + dinv/selfn/c + zero, one block ----------------
__global__ void k_scandinv(const int* __restrict__ dst) {
    __shared__ int cnt[2048];
    __shared__ int s[2048];
    int t = threadIdx.x;                 // 1024 threads
    cnt[t] = 0; cnt[t + 1024] = 0;
    __syncthreads();
    for (int e = t; e < NE; e += 1024) atomicAdd(&cnt[dst[e]], 1);
    __syncthreads();
    for (int i = t; i < NN; i += 1024) {
        float di = rsqrtf((float)(cnt[i] + 1));
        g_dinv[i]  = di;
        float sn   = di * di;
        g_selfn[i] = sn;
        g_c[i]     = sn;
        g_cursor[i] = 0;
    }
    s[t] = cnt[t]; s[t + 1024] = cnt[t + 1024];
    __syncthreads();
    for (int off = 1; off < 2048; off <<= 1) {
        int v0 = (t >= off) ? s[t - off] : 0;
        int v1 = s[t + 1024 - off];
        __syncthreads();
        s[t] += v0;
        s[t + 1024] += v1;
        __syncthreads();
    }
    if (t == 0) g_rs[0] = 0;
    if (t < NN) g_rs[t + 1] = s[t];
    if (t + 1024 < NN) g_rs[t + 1025] = s[t + 1024];
    for (int i = t; i < NB * ND; i += 1024) g_v[i] = 0.f;
}

__global__ void k_scatter(const int* __restrict__ src, const int* __restrict__ dst) {
    int e = blockIdx.x * blockDim.x + threadIdx.x;
    if (e < NE) {
        int dd = dst[e], ss = src[e];
        float w = g_dinv[ss] * g_dinv[dd];
        int p = g_rs[dd] + atomicAdd(&g_cursor[dd], 1);
        __half2 hw = __floats2half2_rn(w, w);
        g_csr[p] = make_int2(ss * 16, *reinterpret_cast<int*>(&hw));
        atomicAdd(&g_c[ss], w);
    }
}

// ---------------- GEMM1 via mma.sync (HMMA): h1 = X @ W1, fp16 in, fp32 acc ----------------
#define AS_STRIDE 132

__device__ __forceinline__ void mma16816(float* c, const uint32_t* a, const uint32_t* b) {
    asm volatile(
        "mma.sync.aligned.m16n8k16.row.col.f32.f16.f16.f32 "
        "{%0,%1,%2,%3}, {%4,%5,%6,%7}, {%8,%9}, {%0,%1,%2,%3};"
        : "+f"(c[0]), "+f"(c[1]), "+f"(c[2]), "+f"(c[3])
        : "r"(a[0]), "r"(a[1]), "r"(a[2]), "r"(a[3]), "r"(b[0]), "r"(b[1]));
}

__global__ void __launch_bounds__(256, 1)
k_gemm_mma(const float* __restrict__ X, const float* __restrict__ W1) {
    __shared__ __half As[128 * AS_STRIDE];
    __shared__ __half Bs[128 * AS_STRIDE];   // Bs[n][k] = W1[k][n]
    int tid = threadIdx.x;
    int wid = tid >> 5, lane = tid & 31;
    size_t row0 = (size_t)blockIdx.x * 128;

#pragma unroll
    for (int i = 0; i < 32; i++) {
        int idx = tid + i * 256;
        int row = idx >> 6, c2 = idx & 63;
        float2 xv = *(const float2*)(X + (row0 + row) * ND + c2 * 2);
        *(__half2*)(As + row * AS_STRIDE + c2 * 2) = __floats2half2_rn(xv.x, xv.y);
    }
#pragma unroll
    for (int i = 0; i < 64; i++) {
        int idx = tid + i * 256;
        int n = idx & 127, k = idx >> 7;
        Bs[n * AS_STRIDE + k] = __float2half(W1[idx]);
    }
    __syncthreads();

    int wr = (wid & 3) * 32;
    int wc = (wid >> 2) * 64;
    int grp = lane >> 2;
    int tig = lane & 3;

    float acc[2][8][4];
#pragma unroll
    for (int mt = 0; mt < 2; mt++)
#pragma unroll
        for (int nt = 0; nt < 8; nt++)
#pragma unroll
            for (int q = 0; q < 4; q++) acc[mt][nt][q] = 0.f;

#pragma unroll
    for (int kc = 0; kc < 8; kc++) {
        int k0 = kc * 16;
        uint32_t a[2][4];
#pragma unroll
        for (int mt = 0; mt < 2; mt++) {
            const __half* base = As + (wr + mt * 16) * AS_STRIDE + k0;
            a[mt][0] = *(const uint32_t*)(base + grp * AS_STRIDE + tig * 2);
            a[mt][1] = *(const uint32_t*)(base + (grp + 8) * AS_STRIDE + tig * 2);
            a[mt][2] = *(const uint32_t*)(base + grp * AS_STRIDE + tig * 2 + 8);
            a[mt][3] = *(const uint32_t*)(base + (grp + 8) * AS_STRIDE + tig * 2 + 8);
        }
#pragma unroll
        for (int nt = 0; nt < 8; nt++) {
            uint32_t b[2];
            const __half* bb = Bs + (wc + nt * 8 + grp) * AS_STRIDE + k0;
            b[0] = *(const uint32_t*)(bb + tig * 2);
            b[1] = *(const uint32_t*)(bb + tig * 2 + 8);
            mma16816(acc[0][nt], a[0], b);
            mma16816(acc[1][nt], a[1], b);
        }
    }

#pragma unroll
    for (int mt = 0; mt < 2; mt++) {
        size_t r0 = row0 + wr + mt * 16 + grp;
#pragma unroll
        for (int nt = 0; nt < 8; nt++) {
            int col = wc + nt * 8 + tig * 2;
            __half2 lo = __floats2half2_rn(acc[mt][nt][0], acc[mt][nt][1]);
            __half2 hi = __floats2half2_rn(acc[mt][nt][2], acc[mt][nt][3]);
            *(__half2*)(g_h1 + r0 * ND + col)       = lo;
            *(__half2*)(g_h1 + (r0 + 8) * ND + col) = hi;
        }
    }
}

// ---------------- agg: 2 batches per warp, parity groups, HFMA2 ----------------
// block = 128 threads (4 warps); warp: WCHUNK dsts x 2 batches; 16 lanes = 128 dims
__global__ void __launch_bounds__(128)
k_agg(const float* __restrict__ b1) {
    int warp = threadIdx.x >> 5, lane = threadIdx.x & 31;
    int hf = lane >> 4;                   // edge-parity group
    int sl = lane & 15;                   // dims 8*sl .. 8*sl+7
    int b0 = blockIdx.y * 2;
    int dst0 = (blockIdx.x * 4 + warp) * WCHUNK;
    int dst1 = min(dst0 + WCHUNK, NN);
    const uint4* __restrict__ hb0 = (const uint4*)(g_h1 + (size_t)b0 * NN * ND);
    const uint4* __restrict__ hb1 = (const uint4*)(g_h1 + (size_t)(b0 + 1) * NN * ND);

    float4 p00 = make_float4(0.f, 0.f, 0.f, 0.f), p01 = p00;  // batch b0 pool acc
    float4 p10 = p00, p11 = p00;                               // batch b0+1

    for (int dst = dst0; dst < dst1; ++dst) {
        int s = g_rs[dst], e = g_rs[dst + 1];
        __half2 z = __floats2half2_rn(0.f, 0.f);
        __half2 a0 = z, a1 = z, a2 = z, a3 = z;   // batch b0
        __half2 c0 = z, c1 = z, c2 = z, c3 = z;   // batch b0+1
        int i = s + hf;
        for (; i + 2 < e; i += 4) {
            int2 eA = g_csr[i], eB = g_csr[i + 2];
            uint4 hA0 = hb0[eA.x + sl];
            uint4 hA1 = hb1[eA.x + sl];
            uint4 hB0 = hb0[eB.x + sl];
            uint4 hB1 = hb1[eB.x + sl];
            __half2 wA = u2h2((unsigned)eA.y), wB = u2h2((unsigned)eB.y);
            a0 = __hfma2(wA, u2h2(hA0.x), a0); a1 = __hfma2(wA, u2h2(hA0.y), a1);
            a2 = __hfma2(wA, u2h2(hA0.z), a2); a3 = __hfma2(wA, u2h2(hA0.w), a3);
            c0 = __hfma2(wA, u2h2(hA1.x), c0); c1 = __hfma2(wA, u2h2(hA1.y), c1);
            c2 = __hfma2(wA, u2h2(hA1.z), c2); c3 = __hfma2(wA, u2h2(hA1.w), c3);
            a0 = __hfma2(wB, u2h2(hB0.x), a0); a1 = __hfma2(wB, u2h2(hB0.y), a1);
            a2 = __hfma2(wB, u2h2(hB0.z), a2); a3 = __hfma2(wB, u2h2(hB0.w), a3);
            c0 = __hfma2(wB, u2h2(hB1.x), c0); c1 = __hfma2(wB, u2h2(hB1.y), c1);
            c2 = __hfma2(wB, u2h2(hB1.z), c2); c3 = __hfma2(wB, u2h2(hB1.w), c3);
        }
        if (i < e) {
            int2 eA = g_csr[i];
            uint4 hA0 = hb0[eA.x + sl];
            uint4 hA1 = hb1[eA.x + sl];
            __half2 wA = u2h2((unsigned)eA.y);
            a0 = __hfma2(wA, u2h2(hA0.x), a0); a1 = __hfma2(wA, u2h2(hA0.y), a1);
            a2 = __hfma2(wA, u2h2(hA0.z), a2); a3 = __hfma2(wA, u2h2(hA0.w), a3);
            c0 = __hfma2(wA, u2h2(hA1.x), c0); c1 = __hfma2(wA, u2h2(hA1.y), c1);
            c2 = __hfma2(wA, u2h2(hA1.z), c2); c3 = __hfma2(wA, u2h2(hA1.w), c3);
        }
        // combine parity groups
#define COMB(r) r = __hadd2(r, u2h2(__shfl_down_sync(0xffffffffu, *(unsigned*)&r, 16)))
        COMB(a0); COMB(a1); COMB(a2); COMB(a3);
        COMB(c0); COMB(c1); COMB(c2); COMB(c3);
#undef COMB

        if (hf == 0) {
            float4 bia = *(const float4*)(b1 + 8 * sl);
            float4 bib = *(const float4*)(b1 + 8 * sl + 4);
            float sn = g_selfn[dst];
            float cc = g_c[dst];
            // batch b0
            {
                uint4 hs = hb0[dst * 16 + sl];
                float2 s0 = __half22float2(u2h2(hs.x));
                float2 s1 = __half22float2(u2h2(hs.y));
                float2 s2 = __half22float2(u2h2(hs.z));
                float2 s3 = __half22float2(u2h2(hs.w));
                float2 f0 = __half22float2(a0);
                float2 f1 = __half22float2(a1);
                float2 f2 = __half22float2(a2);
                float2 f3 = __half22float2(a3);
                p00.x = fmaf(cc, fmaxf(fmaf(sn, s0.x, bia.x) + f0.x, 0.f), p00.x);
                p00.y = fmaf(cc, fmaxf(fmaf(sn, s0.y, bia.y) + f0.y, 0.f), p00.y);
                p00.z = fmaf(cc, fmaxf(fmaf(sn, s1.x, bia.z) + f1.x, 0.f), p00.z);
                p00.w = fmaf(cc, fmaxf(fmaf(sn, s1.y, bia.w) + f1.y, 0.f), p00.w);
                p01.x = fmaf(cc, fmaxf(fmaf(sn, s2.x, bib.x) + f2.x, 0.f), p01.x);
                p01.y = fmaf(cc, fmaxf(fmaf(sn, s2.y, bib.y) + f2.y, 0.f), p01.y);
                p01.z = fmaf(cc, fmaxf(fmaf(sn, s3.x, bib.z) + f3.x, 0.f), p01.z);
                p01.w = fmaf(cc, fmaxf(fmaf(sn, s3.y, bib.w) + f3.y, 0.f), p01.w);
            }
            // batch b0+1
            {
                uint4 hs = hb1[dst * 16 + sl];
                float2 s0 = __half22float2(u2h2(hs.x));
                float2 s1 = __half22float2(u2h2(hs.y));
                float2 s2 = __half22float2(u2h2(hs.z));
                float2 s3 = __half22float2(u2h2(hs.w));
                float2 f0 = __half22float2(c0);
                float2 f1 = __half22float2(c1);
                float2 f2 = __half22float2(c2);
                float2 f3 = __half22float2(c3);
                p10.x = fmaf(cc, fmaxf(fmaf(sn, s0.x, bia.x) + f0.x, 0.f), p10.x);
                p10.y = fmaf(cc, fmaxf(fmaf(sn, s0.y, bia.y) + f0.y, 0.f), p10.y);
                p10.z = fmaf(cc, fmaxf(fmaf(sn, s1.x, bia.z) + f1.x, 0.f), p10.z);
                p10.w = fmaf(cc, fmaxf(fmaf(sn, s1.y, bia.w) + f1.y, 0.f), p10.w);
                p11.x = fmaf(cc, fmaxf(fmaf(sn, s2.x, bib.x) + f2.x, 0.f), p11.x);
                p11.y = fmaf(cc, fmaxf(fmaf(sn, s2.y, bib.y) + f2.y, 0.f), p11.y);
                p11.z = fmaf(cc, fmaxf(fmaf(sn, s3.x, bib.z) + f3.x, 0.f), p11.z);
                p11.w = fmaf(cc, fmaxf(fmaf(sn, s3.y, bib.w) + f3.y, 0.f), p11.w);
            }
        }
    }
    if (hf == 0) {
        float* v0 = g_v + b0 * ND + 8 * sl;
        float* v1 = g_v + (b0 + 1) * ND + 8 * sl;
        atomicAdd(v0 + 0, p00.x); atomicAdd(v0 + 1, p00.y);
        atomicAdd(v0 + 2, p00.z); atomicAdd(v0 + 3, p00.w);
        atomicAdd(v0 + 4, p01.x); atomicAdd(v0 + 5, p01.y);
        atomicAdd(v0 + 6, p01.z); atomicAdd(v0 + 7, p01.w);
        atomicAdd(v1 + 0, p10.x); atomicAdd(v1 + 1, p10.y);
        atomicAdd(v1 + 2, p10.z); atomicAdd(v1 + 3, p10.w);
        atomicAdd(v1 + 4, p11.x); atomicAdd(v1 + 5, p11.y);
        atomicAdd(v1 + 6, p11.z); atomicAdd(v1 + 7, p11.w);
    }
}

// ---------------- final: split-k GEMV, out[b,:] = (v[b,:]/N) @ W2 + b2 ----------------
__global__ void __launch_bounds__(512)
k_final(const float* __restrict__ W2, const float* __restrict__ b2,
        float* __restrict__ out) {
    __shared__ float vs[ND];
    __shared__ float part[3][ND];
    int b = blockIdx.x;
    int tid = threadIdx.x;
    int q = tid >> 7, d = tid & 127;
    if (tid < ND) vs[tid] = g_v[b * ND + tid] * (1.0f / NN);
    __syncthreads();
    float acc = 0.f;
    int k0 = q * 32;
#pragma unroll
    for (int kk = 0; kk < 32; kk++) {
        int k = k0 + kk;
        acc = fmaf(vs[k], W2[k * ND + d], acc);
    }
    if (q > 0) part[q - 1][d] = acc;
    __syncthreads();
    if (q == 0)
        out[b * ND + d] = acc + part[0][d] + part[1][d] + part[2][d] + b2[d];
}

// ---------------- launch ----------------
extern "C" void kernel_launch(void* const* d_in, const int* in_sizes, int n_in,
                              void* d_out, int out_size) {
    const float* gene = (const float*)d_in[0];
    const int*   esrc = (const int*)d_in[1];
    const int*   edst = (const int*)d_in[2];
    const float* W1   = (const float*)d_in[3];
    const float* b1   = (const float*)d_in[4];
    const float* W2   = (const float*)d_in[5];
    const float* b2   = (const float*)d_in[6];
    float* out = (float*)d_out;

    k_scandinv<<<1, 1024>>>(edst);                          // 1
    k_scatter<<<(NE + 255) / 256, 256>>>(esrc, edst);       // 2
    k_gemm_mma<<<(NB * NN) / 128, 256>>>(gene, W1);         // 3
    dim3 agrid((NN + 4 * WCHUNK - 1) / (4 * WCHUNK), NB / 2);  // 100 x 16
    k_agg<<<agrid, 128>>>(b1);                              // 4  <- ncu profiles this
    k_final<<<NB, 512>>>(W2, b2, out);                      // 5
}

// round 13
// speedup vs baseline: 1.1187x; 1.1187x over previous
#include <cuda_runtime.h>
#include <cuda_fp16.h>
#include <cstdint>

#define NB 32
#define NN 2000
#define NE 64000
#define ND 128
#define WCHUNK 10

// ---------------- scratch ----------------
__device__ int    g_cursor[NN];
__device__ float  g_dinv[NN];
__device__ float  g_selfn[NN];
__device__ float  g_c[NN];
__device__ int    g_rs[NN + 1];
__device__ int2   g_csr[NE];            // (src*16 [uint4 units], w packed half2)
__device__ float  g_v[NB * ND];
__device__ __half g_h1[(size_t)NB * NN * ND];  // layer-1 output, fp16 (16.4 MB)

__device__ __forceinline__ __half2 u2h2(unsigned u) { return *reinterpret_cast<__half2*>(&u); }

// ---------------- prep: count(smem) + scan + dinv/selfn/c + zero, one block ----------------
__global__ void k_scandinv(const int* __restrict__ dst) {
    __shared__ int cnt[2048];
    __shared__ int s[2048];
    int t = threadIdx.x;                 // 1024 threads
    cnt[t] = 0; cnt[t + 1024] = 0;
    __syncthreads();
    for (int e = t; e < NE; e += 1024) atomicAdd(&cnt[dst[e]], 1);
    __syncthreads();
    for (int i = t; i < NN; i += 1024) {
        float di = rsqrtf((float)(cnt[i] + 1));
        g_dinv[i]  = di;
        float sn   = di * di;
        g_selfn[i] = sn;
        g_c[i]     = sn;
        g_cursor[i] = 0;
    }
    s[t] = cnt[t]; s[t + 1024] = cnt[t + 1024];
    __syncthreads();
    for (int off = 1; off < 2048; off <<= 1) {
        int v0 = (t >= off) ? s[t - off] : 0;
        int v1 = s[t + 1024 - off];
        __syncthreads();
        s[t] += v0;
        s[t + 1024] += v1;
        __syncthreads();
    }
    if (t == 0) g_rs[0] = 0;
    if (t < NN) g_rs[t + 1] = s[t];
    if (t + 1024 < NN) g_rs[t + 1025] = s[t + 1024];
    for (int i = t; i < NB * ND; i += 1024) g_v[i] = 0.f;
}

__global__ void k_scatter(const int* __restrict__ src, const int* __restrict__ dst) {
    int e = blockIdx.x * blockDim.x + threadIdx.x;
    if (e < NE) {
        int dd = dst[e], ss = src[e];
        float w = g_dinv[ss] * g_dinv[dd];
        int p = g_rs[dd] + atomicAdd(&g_cursor[dd], 1);
        __half2 hw = __floats2half2_rn(w, w);
        g_csr[p] = make_int2(ss * 16, *reinterpret_cast<int*>(&hw));
        atomicAdd(&g_c[ss], w);
    }
}

// ---------------- GEMM1 via mma.sync (HMMA): h1 = X @ W1, fp16 in, fp32 acc ----------------
#define AS_STRIDE 132

__device__ __forceinline__ void mma16816(float* c, const uint32_t* a, const uint32_t* b) {
    asm volatile(
        "mma.sync.aligned.m16n8k16.row.col.f32.f16.f16.f32 "
        "{%0,%1,%2,%3}, {%4,%5,%6,%7}, {%8,%9}, {%0,%1,%2,%3};"
        : "+f"(c[0]), "+f"(c[1]), "+f"(c[2]), "+f"(c[3])
        : "r"(a[0]), "r"(a[1]), "r"(a[2]), "r"(a[3]), "r"(b[0]), "r"(b[1]));
}

__global__ void __launch_bounds__(256, 1)
k_gemm_mma(const float* __restrict__ X, const float* __restrict__ W1) {
    __shared__ __half As[128 * AS_STRIDE];
    __shared__ __half Bs[128 * AS_STRIDE];   // Bs[n][k] = W1[k][n]
    int tid = threadIdx.x;
    int wid = tid >> 5, lane = tid & 31;
    size_t row0 = (size_t)blockIdx.x * 128;

#pragma unroll
    for (int i = 0; i < 32; i++) {
        int idx = tid + i * 256;
        int row = idx >> 6, c2 = idx & 63;
        float2 xv = *(const float2*)(X + (row0 + row) * ND + c2 * 2);
        *(__half2*)(As + row * AS_STRIDE + c2 * 2) = __floats2half2_rn(xv.x, xv.y);
    }
#pragma unroll
    for (int i = 0; i < 64; i++) {
        int idx = tid + i * 256;
        int n = idx & 127, k = idx >> 7;
        Bs[n * AS_STRIDE + k] = __float2half(W1[idx]);
    }
    __syncthreads();

    int wr = (wid & 3) * 32;
    int wc = (wid >> 2) * 64;
    int grp = lane >> 2;
    int tig = lane & 3;

    float acc[2][8][4];
#pragma unroll
    for (int mt = 0; mt < 2; mt++)
#pragma unroll
        for (int nt = 0; nt < 8; nt++)
#pragma unroll
            for (int q = 0; q < 4; q++) acc[mt][nt][q] = 0.f;

#pragma unroll
    for (int kc = 0; kc < 8; kc++) {
        int k0 = kc * 16;
        uint32_t a[2][4];
#pragma unroll
        for (int mt = 0; mt < 2; mt++) {
            const __half* base = As + (wr + mt * 16) * AS_STRIDE + k0;
            a[mt][0] = *(const uint32_t*)(base + grp * AS_STRIDE + tig * 2);
            a[mt][1] = *(const uint32_t*)(base + (grp + 8) * AS_STRIDE + tig * 2);
            a[mt][2] = *(const uint32_t*)(base + grp * AS_STRIDE + tig * 2 + 8);
            a[mt][3] = *(const uint32_t*)(base + (grp + 8) * AS_STRIDE + tig * 2 + 8);
        }
#pragma unroll
        for (int nt = 0; nt < 8; nt++) {
            uint32_t b[2];
            const __half* bb = Bs + (wc + nt * 8 + grp) * AS_STRIDE + k0;
            b[0] = *(const uint32_t*)(bb + tig * 2);
            b[1] = *(const uint32_t*)(bb + tig * 2 + 8);
            mma16816(acc[0][nt], a[0], b);
            mma16816(acc[1][nt], a[1], b);
        }
    }

#pragma unroll
    for (int mt = 0; mt < 2; mt++) {
        size_t r0 = row0 + wr + mt * 16 + grp;
#pragma unroll
        for (int nt = 0; nt < 8; nt++) {
            int col = wc + nt * 8 + tig * 2;
            __half2 lo = __floats2half2_rn(acc[mt][nt][0], acc[mt][nt][1]);
            __half2 hi = __floats2half2_rn(acc[mt][nt][2], acc[mt][nt][3]);
            *(__half2*)(g_h1 + r0 * ND + col)       = lo;
            *(__half2*)(g_h1 + (r0 + 8) * ND + col) = hi;
        }
    }
}

// ---------------- agg: parity groups + 2-deep software pipeline ----------------
// block = 128 threads (4 warps); each warp: WCHUNK dsts; 16 lanes = 128 dims
__global__ void __launch_bounds__(128)
k_agg(const float* __restrict__ b1) {
    int warp = threadIdx.x >> 5, lane = threadIdx.x & 31;
    int hf = lane >> 4;                   // edge-parity group
    int sl = lane & 15;                   // dims 8*sl .. 8*sl+7
    int b = blockIdx.y;
    int dst0 = (blockIdx.x * 4 + warp) * WCHUNK;
    int dst1 = min(dst0 + WCHUNK, NN);
    const uint4* __restrict__ hb = (const uint4*)(g_h1 + (size_t)b * NN * ND);
    const __half2 Z = __floats2half2_rn(0.f, 0.f);
    const uint4 Z4 = make_uint4(0u, 0u, 0u, 0u);

    float4 vacc0 = make_float4(0.f, 0.f, 0.f, 0.f);
    float4 vacc1 = make_float4(0.f, 0.f, 0.f, 0.f);

    for (int dst = dst0; dst < dst1; ++dst) {
        int s = g_rs[dst], e = g_rs[dst + 1];
        __half2 a0 = Z, a1 = Z, a2 = Z, a3 = Z;
        int cons = s + hf;                // next edge position this group consumes
        int ld   = s + hf;                // next edge position this group loads

        __half2 w0A, w0B, w1A, w1B;
        uint4 h0A, h0B, h1A, h1B;

        // prime stage 0 (edges ld, ld+2)
        {
            bool vA = ld < e, vB = ld + 2 < e;
            int2 eA = vA ? g_csr[ld]     : make_int2(0, 0);
            int2 eB = vB ? g_csr[ld + 2] : make_int2(0, 0);
            h0A = vA ? hb[eA.x + sl] : Z4;
            h0B = vB ? hb[eB.x + sl] : Z4;
            w0A = vA ? u2h2((unsigned)eA.y) : Z;
            w0B = vB ? u2h2((unsigned)eB.y) : Z;
            ld += 4;
        }
        // prime stage 1 (edges ld, ld+2)
        {
            bool vA = ld < e, vB = ld + 2 < e;
            int2 eA = vA ? g_csr[ld]     : make_int2(0, 0);
            int2 eB = vB ? g_csr[ld + 2] : make_int2(0, 0);
            h1A = vA ? hb[eA.x + sl] : Z4;
            h1B = vB ? hb[eB.x + sl] : Z4;
            w1A = vA ? u2h2((unsigned)eA.y) : Z;
            w1B = vB ? u2h2((unsigned)eB.y) : Z;
            ld += 4;
        }

        while (cons < e) {
            // refill-then-consume stage 0
            {
                bool vA = ld < e, vB = ld + 2 < e;
                int2 eA = vA ? g_csr[ld]     : make_int2(0, 0);
                int2 eB = vB ? g_csr[ld + 2] : make_int2(0, 0);
                uint4 nA = vA ? hb[eA.x + sl] : Z4;
                uint4 nB = vB ? hb[eB.x + sl] : Z4;
                a0 = __hfma2(w0A, u2h2(h0A.x), a0); a1 = __hfma2(w0A, u2h2(h0A.y), a1);
                a2 = __hfma2(w0A, u2h2(h0A.z), a2); a3 = __hfma2(w0A, u2h2(h0A.w), a3);
                a0 = __hfma2(w0B, u2h2(h0B.x), a0); a1 = __hfma2(w0B, u2h2(h0B.y), a1);
                a2 = __hfma2(w0B, u2h2(h0B.z), a2); a3 = __hfma2(w0B, u2h2(h0B.w), a3);
                w0A = vA ? u2h2((unsigned)eA.y) : Z;
                w0B = vB ? u2h2((unsigned)eB.y) : Z;
                h0A = nA; h0B = nB;
                ld += 4; cons += 4;
            }
            if (cons >= e) break;
            // refill-then-consume stage 1
            {
                bool vA = ld < e, vB = ld + 2 < e;
                int2 eA = vA ? g_csr[ld]     : make_int2(0, 0);
                int2 eB = vB ? g_csr[ld + 2] : make_int2(0, 0);
                uint4 nA = vA ? hb[eA.x + sl] : Z4;
                uint4 nB = vB ? hb[eB.x + sl] : Z4;
                a0 = __hfma2(w1A, u2h2(h1A.x), a0); a1 = __hfma2(w1A, u2h2(h1A.y), a1);
                a2 = __hfma2(w1A, u2h2(h1A.z), a2); a3 = __hfma2(w1A, u2h2(h1A.w), a3);
                a0 = __hfma2(w1B, u2h2(h1B.x), a0); a1 = __hfma2(w1B, u2h2(h1B.y), a1);
                a2 = __hfma2(w1B, u2h2(h1B.z), a2); a3 = __hfma2(w1B, u2h2(h1B.w), a3);
                w1A = vA ? u2h2((unsigned)eA.y) : Z;
                w1B = vB ? u2h2((unsigned)eB.y) : Z;
                h1A = nA; h1B = nB;
                ld += 4; cons += 4;
            }
        }

        // combine the two edge-parity groups
#define COMB(r) r = __hadd2(r, u2h2(__shfl_down_sync(0xffffffffu, *(unsigned*)&r, 16)))
        COMB(a0); COMB(a1); COMB(a2); COMB(a3);
#undef COMB

        if (hf == 0) {
            uint4 hs = hb[dst * 16 + sl];
            float2 s0 = __half22float2(u2h2(hs.x));
            float2 s1 = __half22float2(u2h2(hs.y));
            float2 s2 = __half22float2(u2h2(hs.z));
            float2 s3 = __half22float2(u2h2(hs.w));
            float2 f0 = __half22float2(a0);
            float2 f1 = __half22float2(a1);
            float2 f2 = __half22float2(a2);
            float2 f3 = __half22float2(a3);
            float4 bia = *(const float4*)(b1 + 8 * sl);
            float4 bib = *(const float4*)(b1 + 8 * sl + 4);
            float sn = g_selfn[dst];
            float c  = g_c[dst];
            float t0 = fmaf(sn, s0.x, bia.x) + f0.x;
            float t1 = fmaf(sn, s0.y, bia.y) + f0.y;
            float t2 = fmaf(sn, s1.x, bia.z) + f1.x;
            float t3 = fmaf(sn, s1.y, bia.w) + f1.y;
            float t4 = fmaf(sn, s2.x, bib.x) + f2.x;
            float t5 = fmaf(sn, s2.y, bib.y) + f2.y;
            float t6 = fmaf(sn, s3.x, bib.z) + f3.x;
            float t7 = fmaf(sn, s3.y, bib.w) + f3.y;
            vacc0.x = fmaf(c, fmaxf(t0, 0.f), vacc0.x);
            vacc0.y = fmaf(c, fmaxf(t1, 0.f), vacc0.y);
            vacc0.z = fmaf(c, fmaxf(t2, 0.f), vacc0.z);
            vacc0.w = fmaf(c, fmaxf(t3, 0.f), vacc0.w);
            vacc1.x = fmaf(c, fmaxf(t4, 0.f), vacc1.x);
            vacc1.y = fmaf(c, fmaxf(t5, 0.f), vacc1.y);
            vacc1.z = fmaf(c, fmaxf(t6, 0.f), vacc1.z);
            vacc1.w = fmaf(c, fmaxf(t7, 0.f), vacc1.w);
        }
    }
    if (hf == 0) {
        float* vb = g_v + b * ND + 8 * sl;
        atomicAdd(vb + 0, vacc0.x);
        atomicAdd(vb + 1, vacc0.y);
        atomicAdd(vb + 2, vacc0.z);
        atomicAdd(vb + 3, vacc0.w);
        atomicAdd(vb + 4, vacc1.x);
        atomicAdd(vb + 5, vacc1.y);
        atomicAdd(vb + 6, vacc1.z);
        atomicAdd(vb + 7, vacc1.w);
    }
}

// ---------------- final: split-k GEMV, out[b,:] = (v[b,:]/N) @ W2 + b2 ----------------
__global__ void __launch_bounds__(512)
k_final(const float* __restrict__ W2, const float* __restrict__ b2,
        float* __restrict__ out) {
    __shared__ float vs[ND];
    __shared__ float part[3][ND];
    int b = blockIdx.x;
    int tid = threadIdx.x;
    int q = tid >> 7, d = tid & 127;
    if (tid < ND) vs[tid] = g_v[b * ND + tid] * (1.0f / NN);
    __syncthreads();
    float acc = 0.f;
    int k0 = q * 32;
#pragma unroll
    for (int kk = 0; kk < 32; kk++) {
        int k = k0 + kk;
        acc = fmaf(vs[k], W2[k * ND + d], acc);
    }
    if (q > 0) part[q - 1][d] = acc;
    __syncthreads();
    if (q == 0)
        out[b * ND + d] = acc + part[0][d] + part[1][d] + part[2][d] + b2[d];
}

// ---------------- launch ----------------
extern "C" void kernel_launch(void* const* d_in, const int* in_sizes, int n_in,
                              void* d_out, int out_size) {
    const float* gene = (const float*)d_in[0];
    const int*   esrc = (const int*)d_in[1];
    const int*   edst = (const int*)d_in[2];
    const float* W1   = (const float*)d_in[3];
    const float* b1   = (const float*)d_in[4];
    const float* W2   = (const float*)d_in[5];
    const float* b2   = (const float*)d_in[6];
    float* out = (float*)d_out;

    k_scandinv<<<1, 1024>>>(edst);                          // 1
    k_scatter<<<(NE + 255) / 256, 256>>>(esrc, edst);       // 2
    k_gemm_mma<<<(NB * NN) / 128, 256>>>(gene, W1);         // 3
    dim3 agrid((NN + 4 * WCHUNK - 1) / (4 * WCHUNK), NB);   // 50 x 32
    k_agg<<<agrid, 128>>>(b1);                              // 4  <- ncu profiles this
    k_final<<<NB, 512>>>(W2, b2, out);                      // 5
}